// round 12
// baseline (speedup 1.0000x reference)
#include <cuda_runtime.h>
#include <cuda_bf16.h>
#include <math.h>

// Problem constants
#define PB  32
#define PM  10
#define PN  1000
#define MN  1010          // M + N
#define PD  128
#define NODES_TOTAL (PB*MN*PD)   // 4,136,960

// k_comb tiling: 8 warps/block, one warp per j, JPW j's per warp
#define JPW 6
#define JPB (8*JPW)                       // 48 j's per block
#define JTILES ((MN + JPB - 1) / JPB)     // 22  (tiles 0..20 full, 21 = tail)

// Scratch (device globals — no allocation allowed)
__device__ __align__(16) float g_vpref[PD];      // Wp @ W_pref[:,0]
__device__ __align__(16) float g_Wnc[PD*5];      // Wn @ W_clients (128x5)
__device__ __align__(16) float g_Wna[PD*4];      // Wn @ W_agents  (128x4)
__device__ __align__(16) float g_A[PB*PM*PD];    // agent broadcast term (B*M x 128)

// ---------------------------------------------------------------------------
// k_pre: folds + agent A-chain. grid = 480 blocks x 256 threads.
//  [0,160)   : weight folds (one warp per dot-128 output: vpref / Wnc / Wna)
//  [160,480) : per-(b,i) agent A-chain -> g_A
// ---------------------------------------------------------------------------
__global__ void __launch_bounds__(256) k_pre(
                      const float* __restrict__ Wpp,    // W_posproj (128x128)
                      const float* __restrict__ alpha,  // (1,)
                      const float* __restrict__ Wfin,   // W_final (128x384)
                      const float* __restrict__ Wpref,  // W_pref (128x1)
                      const float* __restrict__ Wc,     // W_clients (128x5)
                      const float* __restrict__ Wa,     // W_agents (128x4)
                      const float* __restrict__ locs,   // (B,1010,2)
                      const float* __restrict__ cap,    // (B,10)
                      const float* __restrict__ spd,    // (B,10)
                      const float* __restrict__ Wdep,   // W_depot (128x2)
                      const float* __restrict__ Wda)    // W_depot_agents (128x256)
{
    const int lane = threadIdx.x & 31;
    const int warp = threadIdx.x >> 5;    // 0..7

    if (blockIdx.x < 160) {
        // ---------------- weight folds ----------------
        const int t = blockIdx.x * 8 + warp;
        float s = 0.f;
        if (t < 128) {
            const int d1 = t;
            #pragma unroll
            for (int q = 0; q < 4; q++) {
                int e = lane + 32 * q;
                s += Wfin[d1 * 384 + 128 + e] * Wpref[e];
            }
            #pragma unroll
            for (int o = 16; o; o >>= 1) s += __shfl_xor_sync(0xffffffffu, s, o);
            if (lane == 0) g_vpref[d1] = s;
        } else if (t < 768) {
            const int o = t - 128, d1 = o / 5, k = o % 5;
            #pragma unroll
            for (int q = 0; q < 4; q++) {
                int e = lane + 32 * q;
                s += Wfin[d1 * 384 + e] * __ldg(&Wc[e * 5 + k]);
            }
            #pragma unroll
            for (int off = 16; off; off >>= 1) s += __shfl_xor_sync(0xffffffffu, s, off);
            if (lane == 0) g_Wnc[o] = s;
        } else {
            const int o = t - 768, d1 = o / 4, k = o % 4;
            #pragma unroll
            for (int q = 0; q < 4; q++) {
                int e = lane + 32 * q;
                s += Wfin[d1 * 384 + e] * __ldg(&Wa[e * 4 + k]);
            }
            #pragma unroll
            for (int off = 16; off; off >>= 1) s += __shfl_xor_sync(0xffffffffu, s, off);
            if (lane == 0) g_Wna[o] = s;
        }
        return;
    }

    // ---------------- agent A-chain: one block per (b, i) ----------------
    const int idx = blockIdx.x - 160;     // 0..319
    const int b = idx / PM;
    const int i = idx % PM;
    const int tid = threadIdx.x;

    __shared__ float spe[PD], sde[PD], sae[PD], sdA[PD];

    const float lx = __ldg(&locs[(b * MN + i) * 2 + 0]);
    const float ly = __ldg(&locs[(b * MN + i) * 2 + 1]);
    const float c  = __ldg(&cap[b * PM + i]) * (1.0f / 40.0f);
    const float sp = __ldg(&spd[b * PM + i]);

    if (tid < PD) {
        sae[tid] = lx * Wa[tid * 4 + 0] + ly * Wa[tid * 4 + 1]
                 + c  * Wa[tid * 4 + 2] + sp * Wa[tid * 4 + 3];
        const float nl = -logf(10000.0f) / (float)PD;
        int k2 = (tid >> 1) * 2;
        float ang = (float)i * expf((float)k2 * nl);
        spe[tid] = (tid & 1) ? cosf(ang) : sinf(ang);
    }
    __syncthreads();

    const float a0 = __ldg(&alpha[0]);
    for (int r = 0; r < 16; r++) {
        int d1 = warp * 16 + r;
        float s = 0.f;
        #pragma unroll
        for (int q = 0; q < 4; q++) {
            int e = lane + 32 * q;
            s += spe[e] * Wpp[d1 * PD + e];
        }
        #pragma unroll
        for (int off = 16; off; off >>= 1) s += __shfl_xor_sync(0xffffffffu, s, off);
        if (lane == 0)
            sde[d1] = lx * Wdep[d1 * 2 + 0] + ly * Wdep[d1 * 2 + 1] + a0 * s;
    }
    __syncthreads();

    for (int r = 0; r < 16; r++) {
        int d1 = warp * 16 + r;
        float s = 0.f;
        #pragma unroll
        for (int q = 0; q < 4; q++) {
            int e = lane + 32 * q;
            s += sde[e] * Wda[d1 * 256 + e] + sae[e] * Wda[d1 * 256 + 128 + e];
        }
        #pragma unroll
        for (int off = 16; off; off >>= 1) s += __shfl_xor_sync(0xffffffffu, s, off);
        if (lane == 0) sdA[d1] = s;
    }
    __syncthreads();

    for (int r = 0; r < 16; r++) {
        int d1 = warp * 16 + r;
        float s = 0.f;
        #pragma unroll
        for (int q = 0; q < 4; q++) {
            int e = lane + 32 * q;
            s += sdA[e] * Wfin[d1 * 384 + 256 + e];
        }
        #pragma unroll
        for (int off = 16; off; off >>= 1) s += __shfl_xor_sync(0xffffffffu, s, off);
        if (lane == 0) g_A[(b * PM + i) * PD + d1] = s;
    }
}

// ---------------------------------------------------------------------------
// k_nodes: nodes_embedding rows ONLY. Fully independent of k_pre/k_comb
// (reads raw inputs, writes out[0..NODES_TOTAL)). Runs on a side stream.
// grid = 1010 blocks x 256 threads; one warp per 4 node slots.
// ---------------------------------------------------------------------------
__global__ void __launch_bounds__(256) k_nodes(
                      const float* __restrict__ locs,   // (B,1010,2)
                      const float* __restrict__ cap,    // (B,10)
                      const float* __restrict__ spd,    // (B,10)
                      const float* __restrict__ demand, // (B,1,1010)
                      const float* __restrict__ Wa,     // W_agents (128x4)
                      const float* __restrict__ Wc,     // W_clients (128x5)
                      float* __restrict__ out)
{
    const int lane = threadIdx.x & 31;
    const int warp = threadIdx.x >> 5;
    const int g = blockIdx.x * 8 + warp;      // 0..8079
    const int start = g * 4;                  // 4 nodes per warp
    const int d0 = lane * 4;

    float wcl[4][5];
    #pragma unroll
    for (int r = 0; r < 4; r++)
        #pragma unroll
        for (int k = 0; k < 5; k++)
            wcl[r][k] = __ldg(&Wc[(d0 + r) * 5 + k]);

    const float2* locs2 = reinterpret_cast<const float2*>(locs);

    #pragma unroll
    for (int u = 0; u < 4; u++) {
        const int gg = start + u;
        const int b  = gg / MN;
        const int j  = gg - b * MN;

        const float2 l = __ldg(&locs2[b * MN + j]);
        const float lx = l.x, ly = l.y;

        float ne[4];

        if (j < PM) {
            const float c  = __ldg(&cap[b * PM + j]) * (1.0f / 40.0f);
            const float sp = __ldg(&spd[b * PM + j]);
            #pragma unroll
            for (int r = 0; r < 4; r++) {
                const int d = d0 + r;
                ne[r] = lx * __ldg(&Wa[d * 4 + 0]) + ly * __ldg(&Wa[d * 4 + 1])
                      + c  * __ldg(&Wa[d * 4 + 2]) + sp * __ldg(&Wa[d * 4 + 3]);
            }
        } else {
            const float2 dep = __ldg(&locs2[b * MN]);
            const float dx = lx - dep.x;
            const float dy = ly - dep.y;
            const float dist = sqrtf(dx * dx + dy * dy);
            const float ang  = atan2f(dy, dx);
            const float dem  = __ldg(&demand[b * MN + j]) * (1.0f / 40.0f);
            #pragma unroll
            for (int r = 0; r < 4; r++)
                ne[r] = lx  * wcl[r][0] + ly  * wcl[r][1] + dem * wcl[r][2]
                      + dist * wcl[r][3] + ang * wcl[r][4];
        }

        __stcs(reinterpret_cast<float4*>(&out[gg * PD + d0]),
               make_float4(ne[0], ne[1], ne[2], ne[3]));
    }
}

// ---------------------------------------------------------------------------
// k_comb: combined embedding, pipelined, features computed INLINE.
// grid = (JTILES=22, PB=32); block = 256 (8 warps), one warp per j row.
// Full tiles branch-free with next-j raw loads (locs/demand/pref) issued
// before the current store burst. Tail tile checked.
// ---------------------------------------------------------------------------
__global__ void __launch_bounds__(256) k_comb(
                       const float* __restrict__ locs,    // (B,1010,2)
                       const float* __restrict__ cap,     // (B,10)
                       const float* __restrict__ spd,     // (B,10)
                       const float* __restrict__ demand,  // (B,1,1010)
                       const float* __restrict__ pref,    // (B,10,1010)
                       float* __restrict__ out)
{
    const int b    = blockIdx.y;
    const int jt   = blockIdx.x;
    const int lane = threadIdx.x & 31;
    const int warp = threadIdx.x >> 5;
    const int d0   = lane * 4;

    // Per-thread register state
    const float4 vp = *reinterpret_cast<const float4*>(&g_vpref[d0]);

    float wnc[4][5];
    #pragma unroll
    for (int r = 0; r < 4; r++)
        #pragma unroll
        for (int k = 0; k < 5; k++)
            wnc[r][k] = g_Wnc[(d0 + r) * 5 + k];

    float4 a[PM];
    #pragma unroll
    for (int i = 0; i < PM; i++)
        a[i] = *reinterpret_cast<const float4*>(&g_A[(b * PM + i) * PD + d0]);

    const float2* locs2 = reinterpret_cast<const float2*>(locs);
    const float2 dep = __ldg(&locs2[b * MN]);

    float* __restrict__ out2 = out + NODES_TOTAL;
    const int jbase = jt * JPB + warp;     // first j for this warp (stride 8)

    if (jt < JTILES - 1) {
        // ================= full tile: branch-free, pipelined =================
        float2 lb;  float db;  float pb[PM];

        // prime buffers with j(t=0)
        {
            const int nj = b * MN + jbase;
            lb = __ldg(&locs2[nj]);
            db = __ldg(&demand[nj]);
            #pragma unroll
            for (int i = 0; i < PM; i++)
                pb[i] = __ldg(&pref[(b * PM + i) * MN + jbase]);
        }

        #pragma unroll
        for (int t = 0; t < JPW; t++) {
            const int j = jbase + 8 * t;

            // take current values from the buffers
            const float lx = lb.x, ly = lb.y;
            const float dem = db * (1.0f / 40.0f);
            float p[PM];
            #pragma unroll
            for (int i = 0; i < PM; i++) p[i] = pb[i];

            // issue NEXT j's loads before this j's compute + stores
            if (t < JPW - 1) {
                const int jn = j + 8;
                const int njn = b * MN + jn;
                lb = __ldg(&locs2[njn]);
                db = __ldg(&demand[njn]);
                #pragma unroll
                for (int i = 0; i < PM; i++)
                    pb[i] = __ldg(&pref[(b * PM + i) * MN + jn]);
            }

            float nw[4];
            if (j < PM) {     // only possible in tile 0 (cold path)
                const float c  = __ldg(&cap[b * PM + j]) * (1.0f / 40.0f);
                const float sp = __ldg(&spd[b * PM + j]);
                #pragma unroll
                for (int r = 0; r < 4; r++) {
                    const int d = d0 + r;
                    nw[r] = lx * __ldg(&g_Wna[d * 4 + 0]) + ly * __ldg(&g_Wna[d * 4 + 1])
                          + c  * __ldg(&g_Wna[d * 4 + 2]) + sp * __ldg(&g_Wna[d * 4 + 3]);
                }
            } else {
                const float dx = lx - dep.x;
                const float dy = ly - dep.y;
                const float dist = sqrtf(dx * dx + dy * dy);
                const float ang  = atan2f(dy, dx);
                #pragma unroll
                for (int r = 0; r < 4; r++)
                    nw[r] = lx * wnc[r][0] + ly * wnc[r][1] + dem * wnc[r][2]
                          + dist * wnc[r][3] + ang * wnc[r][4];
            }

            #pragma unroll
            for (int i = 0; i < PM; i++) {
                float4 v;
                v.x = nw[0] + p[i] * vp.x + a[i].x;
                v.y = nw[1] + p[i] * vp.y + a[i].y;
                v.z = nw[2] + p[i] * vp.z + a[i].z;
                v.w = nw[3] + p[i] * vp.w + a[i].w;
                __stcs(reinterpret_cast<float4*>(
                           &out2[((b * PM + i) * MN + j) * PD + d0]), v);
            }
        }
    } else {
        // ================= tail tile: checked =================
        #pragma unroll
        for (int t = 0; t < JPW; t++) {
            const int j = jbase + 8 * t;
            if (j >= MN) break;

            const int nj = b * MN + j;
            const float2 l = __ldg(&locs2[nj]);
            const float dem = __ldg(&demand[nj]) * (1.0f / 40.0f);
            const float dx = l.x - dep.x;
            const float dy = l.y - dep.y;
            const float dist = sqrtf(dx * dx + dy * dy);
            const float ang  = atan2f(dy, dx);

            float nw[4];
            #pragma unroll
            for (int r = 0; r < 4; r++)
                nw[r] = l.x * wnc[r][0] + l.y * wnc[r][1] + dem * wnc[r][2]
                      + dist * wnc[r][3] + ang * wnc[r][4];

            float p[PM];
            #pragma unroll
            for (int i = 0; i < PM; i++)
                p[i] = __ldg(&pref[(b * PM + i) * MN + j]);

            #pragma unroll
            for (int i = 0; i < PM; i++) {
                float4 v;
                v.x = nw[0] + p[i] * vp.x + a[i].x;
                v.y = nw[1] + p[i] * vp.y + a[i].y;
                v.z = nw[2] + p[i] * vp.z + a[i].z;
                v.w = nw[3] + p[i] * vp.w + a[i].w;
                __stcs(reinterpret_cast<float4*>(
                           &out2[((b * PM + i) * MN + j) * PD + d0]), v);
            }
        }
    }
}

// ---------------------------------------------------------------------------
extern "C" void kernel_launch(void* const* d_in, const int* in_sizes, int n_in,
                              void* d_out, int out_size)
{
    const float* locs      = (const float*)d_in[0];
    const float* capacity  = (const float*)d_in[1];
    const float* speed     = (const float*)d_in[2];
    const float* demand    = (const float*)d_in[3];
    const float* pref      = (const float*)d_in[4];
    // d_in[5] = action_mask (bool) — unused
    const float* W_depot   = (const float*)d_in[6];
    const float* W_posproj = (const float*)d_in[7];
    const float* alpha     = (const float*)d_in[8];
    const float* W_agents  = (const float*)d_in[9];
    const float* W_da      = (const float*)d_in[10];
    const float* W_clients = (const float*)d_in[11];
    const float* W_pref    = (const float*)d_in[12];
    const float* W_final   = (const float*)d_in[13];
    float* out = (float*)d_out;

    // Host-side stream/event objects, created once (not device memory).
    static cudaStream_t s_side = nullptr;
    static cudaEvent_t  ev_fork = nullptr, ev_join = nullptr;
    if (s_side == nullptr) {
        cudaStreamCreateWithFlags(&s_side, cudaStreamNonBlocking);
        cudaEventCreateWithFlags(&ev_fork, cudaEventDisableTiming);
        cudaEventCreateWithFlags(&ev_join, cudaEventDisableTiming);
    }

    // Fork: side stream writes the independent nodes_embedding region
    // concurrently with the main-stream fold/A-chain + combined kernel.
    cudaEventRecord(ev_fork, 0);
    cudaStreamWaitEvent(s_side, ev_fork, 0);
    k_nodes<<<1010, 256, 0, s_side>>>(locs, capacity, speed, demand,
                                      W_agents, W_clients, out);
    cudaEventRecord(ev_join, s_side);

    // Main stream: folds + A-chain, then the big combined kernel.
    k_pre<<<480, 256>>>(W_posproj, alpha, W_final, W_pref, W_clients, W_agents,
                        locs, capacity, speed, W_depot, W_da);

    dim3 grid(JTILES, PB);
    k_comb<<<grid, 256>>>(locs, capacity, speed, demand, pref, out);

    // Join: subsequent work (harness end-of-capture) depends on both branches.
    cudaStreamWaitEvent(0, ev_join, 0);
}

// round 13
// speedup vs baseline: 1.1265x; 1.1265x over previous
#include <cuda_runtime.h>
#include <cuda_bf16.h>
#include <math.h>

// Problem constants
#define PB  32
#define PM  10
#define PN  1000
#define MN  1010          // M + N
#define PD  128
#define NODES_TOTAL (PB*MN*PD)   // 4,136,960

// main kernel tiling
#define JPW 6
#define JPB (8*JPW)                       // 48 j's per comb block
#define JTILES ((MN + JPB - 1) / JPB)     // 22  (tiles 0..20 full, 21 = tail)
#define COMB_BLKS (JTILES*PB)             // 704
#define NODE_BLKS 1010                    // 8 warps x 4 nodes = 32 nodes/block
#define MAIN_BLKS (COMB_BLKS + NODE_BLKS) // 1714

// k_pre partition: folds 160, A-chain 320, feats 127
#define PRE_FOLD  160
#define PRE_AGENT 320
#define PRE_FEAT  127                     // 127*256 = 32512 >= 32320
#define PRE_BLKS  (PRE_FOLD + PRE_AGENT + PRE_FEAT)

// Scratch (device globals — no allocation allowed)
__device__ __align__(16) float g_vpref[PD];      // Wp @ W_pref[:,0]
__device__ __align__(16) float g_Wnc[PD*5];      // Wn @ W_clients (128x5)
__device__ __align__(16) float g_Wna[PD*4];      // Wn @ W_agents  (128x4)
__device__ __align__(16) float g_A[PB*PM*PD];    // agent broadcast term (B*M x 128)
// Per-node feature scalars, SoA: [0]=x [1]=y [2]=dem_or_cap/40 [3]=dist_or_speed [4]=angle_or_0
__device__ float g_feat[5][PB*MN];

// ---------------------------------------------------------------------------
// k_pre: folds + A-chain + thread-per-node features. 607 blocks x 256 thr.
// ---------------------------------------------------------------------------
__global__ void __launch_bounds__(256) k_pre(
                      const float* __restrict__ Wpp,    // W_posproj (128x128)
                      const float* __restrict__ alpha,  // (1,)
                      const float* __restrict__ Wfin,   // W_final (128x384)
                      const float* __restrict__ Wpref,  // W_pref (128x1)
                      const float* __restrict__ Wc,     // W_clients (128x5)
                      const float* __restrict__ Wa,     // W_agents (128x4)
                      const float* __restrict__ locs,   // (B,1010,2)
                      const float* __restrict__ cap,    // (B,10)
                      const float* __restrict__ spd,    // (B,10)
                      const float* __restrict__ demand, // (B,1,1010)
                      const float* __restrict__ Wdep,   // W_depot (128x2)
                      const float* __restrict__ Wda)    // W_depot_agents (128x256)
{
    const int lane = threadIdx.x & 31;
    const int warp = threadIdx.x >> 5;    // 0..7

    if (blockIdx.x >= PRE_FOLD + PRE_AGENT) {
        // ---------------- features: one THREAD per node ----------------
        const int gg = (blockIdx.x - (PRE_FOLD + PRE_AGENT)) * 256 + threadIdx.x;
        if (gg >= PB * MN) return;
        const int b = gg / MN;
        const int j = gg - b * MN;

        const float2* locs2 = reinterpret_cast<const float2*>(locs);
        const float2 l = __ldg(&locs2[gg]);
        float f2v, f3v, f4v;

        if (j < PM) {
            f2v = __ldg(&cap[b * PM + j]) * (1.0f / 40.0f);
            f3v = __ldg(&spd[b * PM + j]);
            f4v = 0.f;
        } else {
            const float2 dep = __ldg(&locs2[b * MN]);
            const float dx = l.x - dep.x;
            const float dy = l.y - dep.y;
            f3v = sqrtf(dx * dx + dy * dy);
            f4v = atan2f(dy, dx);
            f2v = __ldg(&demand[gg]) * (1.0f / 40.0f);
        }
        g_feat[0][gg] = l.x;
        g_feat[1][gg] = l.y;
        g_feat[2][gg] = f2v;
        g_feat[3][gg] = f3v;
        g_feat[4][gg] = f4v;
        return;
    }

    if (blockIdx.x < PRE_FOLD) {
        // ---------------- weight folds ----------------
        const int t = blockIdx.x * 8 + warp;
        float s = 0.f;
        if (t < 128) {
            const int d1 = t;
            #pragma unroll
            for (int q = 0; q < 4; q++) {
                int e = lane + 32 * q;
                s += Wfin[d1 * 384 + 128 + e] * Wpref[e];
            }
            #pragma unroll
            for (int o = 16; o; o >>= 1) s += __shfl_xor_sync(0xffffffffu, s, o);
            if (lane == 0) g_vpref[d1] = s;
        } else if (t < 768) {
            const int o = t - 128, d1 = o / 5, k = o % 5;
            #pragma unroll
            for (int q = 0; q < 4; q++) {
                int e = lane + 32 * q;
                s += Wfin[d1 * 384 + e] * __ldg(&Wc[e * 5 + k]);
            }
            #pragma unroll
            for (int off = 16; off; off >>= 1) s += __shfl_xor_sync(0xffffffffu, s, off);
            if (lane == 0) g_Wnc[o] = s;
        } else {
            const int o = t - 768, d1 = o / 4, k = o % 4;
            #pragma unroll
            for (int q = 0; q < 4; q++) {
                int e = lane + 32 * q;
                s += Wfin[d1 * 384 + e] * __ldg(&Wa[e * 4 + k]);
            }
            #pragma unroll
            for (int off = 16; off; off >>= 1) s += __shfl_xor_sync(0xffffffffu, s, off);
            if (lane == 0) g_Wna[o] = s;
        }
        return;
    }

    // ---------------- agent A-chain: one block per (b, i) ----------------
    {
        const int idx = blockIdx.x - PRE_FOLD;     // 0..319
        const int b = idx / PM;
        const int i = idx % PM;
        const int tid = threadIdx.x;

        __shared__ float spe[PD], sde[PD], sae[PD], sdA[PD];

        const float lx = __ldg(&locs[(b * MN + i) * 2 + 0]);
        const float ly = __ldg(&locs[(b * MN + i) * 2 + 1]);
        const float c  = __ldg(&cap[b * PM + i]) * (1.0f / 40.0f);
        const float sp = __ldg(&spd[b * PM + i]);

        if (tid < PD) {
            sae[tid] = lx * Wa[tid * 4 + 0] + ly * Wa[tid * 4 + 1]
                     + c  * Wa[tid * 4 + 2] + sp * Wa[tid * 4 + 3];
            const float nl = -logf(10000.0f) / (float)PD;
            int k2 = (tid >> 1) * 2;
            float ang = (float)i * expf((float)k2 * nl);
            spe[tid] = (tid & 1) ? cosf(ang) : sinf(ang);
        }
        __syncthreads();

        const float a0 = __ldg(&alpha[0]);
        for (int r = 0; r < 16; r++) {
            int d1 = warp * 16 + r;
            float s = 0.f;
            #pragma unroll
            for (int q = 0; q < 4; q++) {
                int e = lane + 32 * q;
                s += spe[e] * Wpp[d1 * PD + e];
            }
            #pragma unroll
            for (int off = 16; off; off >>= 1) s += __shfl_xor_sync(0xffffffffu, s, off);
            if (lane == 0)
                sde[d1] = lx * Wdep[d1 * 2 + 0] + ly * Wdep[d1 * 2 + 1] + a0 * s;
        }
        __syncthreads();

        for (int r = 0; r < 16; r++) {
            int d1 = warp * 16 + r;
            float s = 0.f;
            #pragma unroll
            for (int q = 0; q < 4; q++) {
                int e = lane + 32 * q;
                s += sde[e] * Wda[d1 * 256 + e] + sae[e] * Wda[d1 * 256 + 128 + e];
            }
            #pragma unroll
            for (int off = 16; off; off >>= 1) s += __shfl_xor_sync(0xffffffffu, s, off);
            if (lane == 0) sdA[d1] = s;
        }
        __syncthreads();

        for (int r = 0; r < 16; r++) {
            int d1 = warp * 16 + r;
            float s = 0.f;
            #pragma unroll
            for (int q = 0; q < 4; q++) {
                int e = lane + 32 * q;
                s += sdA[e] * Wfin[d1 * 384 + 256 + e];
            }
            #pragma unroll
            for (int off = 16; off; off >>= 1) s += __shfl_xor_sync(0xffffffffu, s, off);
            if (lane == 0) g_A[(b * PM + i) * PD + d1] = s;
        }
    }
}

// ---------------------------------------------------------------------------
// k_main: ONE launch, flat grid of 1714 blocks x 256 threads.
//  blocks [0,704)      : combined-embedding blocks (R11 pipelined structure;
//                        b = x & 31, jt = x >> 5)
//  blocks [704,1714)   : nodes-row blocks (warp per 4 nodes, g_feat-driven,
//                        no transcendentals) — co-scheduled to fill SM slots
//                        that latency-bound comb blocks leave idle.
// ---------------------------------------------------------------------------
__global__ void __launch_bounds__(256) k_main(
                       const float* __restrict__ pref,    // (B,10,1010)
                       const float* __restrict__ Wa,      // W_agents (128x4)
                       const float* __restrict__ Wc,      // W_clients (128x5)
                       float* __restrict__ out)
{
    const int lane = threadIdx.x & 31;
    const int warp = threadIdx.x >> 5;
    const int d0   = lane * 4;

    if (blockIdx.x >= COMB_BLKS) {
        // ================= nodes blocks =================
        const int n = blockIdx.x - COMB_BLKS;          // 0..1009
        const int start = (n * 8 + warp) * 4;          // first node slot

        // client-row weights in registers
        float wcl[4][5];
        #pragma unroll
        for (int r = 0; r < 4; r++)
            #pragma unroll
            for (int k = 0; k < 5; k++)
                wcl[r][k] = __ldg(&Wc[(d0 + r) * 5 + k]);

        #pragma unroll
        for (int u = 0; u < 4; u++) {
            const int gg = start + u;
            const int j  = gg % MN;

            const float f0 = __ldg(&g_feat[0][gg]);
            const float f1 = __ldg(&g_feat[1][gg]);
            const float f2 = __ldg(&g_feat[2][gg]);
            const float f3 = __ldg(&g_feat[3][gg]);
            const float f4 = __ldg(&g_feat[4][gg]);

            float ne[4];
            if (j < PM) {
                #pragma unroll
                for (int r = 0; r < 4; r++) {
                    const int d = d0 + r;
                    ne[r] = f0 * __ldg(&Wa[d * 4 + 0]) + f1 * __ldg(&Wa[d * 4 + 1])
                          + f2 * __ldg(&Wa[d * 4 + 2]) + f3 * __ldg(&Wa[d * 4 + 3]);
                }
            } else {
                #pragma unroll
                for (int r = 0; r < 4; r++)
                    ne[r] = f0 * wcl[r][0] + f1 * wcl[r][1] + f2 * wcl[r][2]
                          + f3 * wcl[r][3] + f4 * wcl[r][4];
            }

            __stcs(reinterpret_cast<float4*>(&out[gg * PD + d0]),
                   make_float4(ne[0], ne[1], ne[2], ne[3]));
        }
        return;
    }

    // ================= combined blocks (R11 pipelined) =================
    const int b  = blockIdx.x & 31;
    const int jt = blockIdx.x >> 5;

    const float4 vp = *reinterpret_cast<const float4*>(&g_vpref[d0]);

    float wnc[4][5];
    #pragma unroll
    for (int r = 0; r < 4; r++)
        #pragma unroll
        for (int k = 0; k < 5; k++)
            wnc[r][k] = g_Wnc[(d0 + r) * 5 + k];

    float4 a[PM];
    #pragma unroll
    for (int i = 0; i < PM; i++)
        a[i] = *reinterpret_cast<const float4*>(&g_A[(b * PM + i) * PD + d0]);

    float* __restrict__ out2 = out + NODES_TOTAL;
    const int jbase = jt * JPB + warp;     // first j for this warp (stride 8)

    if (jt < JTILES - 1) {
        // ---------- full tile: branch-free, pipelined ----------
        float fb[5], pb[PM];
        {
            const int nj = b * MN + jbase;
            #pragma unroll
            for (int k = 0; k < 5; k++) fb[k] = __ldg(&g_feat[k][nj]);
            #pragma unroll
            for (int i = 0; i < PM; i++)
                pb[i] = __ldg(&pref[(b * PM + i) * MN + jbase]);
        }

        #pragma unroll
        for (int t = 0; t < JPW; t++) {
            const int j = jbase + 8 * t;

            const float f0 = fb[0], f1 = fb[1], f2 = fb[2], f3 = fb[3], f4 = fb[4];
            float p[PM];
            #pragma unroll
            for (int i = 0; i < PM; i++) p[i] = pb[i];

            if (t < JPW - 1) {
                const int jn = j + 8;
                const int njn = b * MN + jn;
                #pragma unroll
                for (int k = 0; k < 5; k++) fb[k] = __ldg(&g_feat[k][njn]);
                #pragma unroll
                for (int i = 0; i < PM; i++)
                    pb[i] = __ldg(&pref[(b * PM + i) * MN + jn]);
            }

            float nw[4];
            if (j < PM) {     // only possible in tile 0
                #pragma unroll
                for (int r = 0; r < 4; r++) {
                    const int d = d0 + r;
                    nw[r] = f0 * __ldg(&g_Wna[d * 4 + 0]) + f1 * __ldg(&g_Wna[d * 4 + 1])
                          + f2 * __ldg(&g_Wna[d * 4 + 2]) + f3 * __ldg(&g_Wna[d * 4 + 3]);
                }
            } else {
                #pragma unroll
                for (int r = 0; r < 4; r++)
                    nw[r] = f0 * wnc[r][0] + f1 * wnc[r][1] + f2 * wnc[r][2]
                          + f3 * wnc[r][3] + f4 * wnc[r][4];
            }

            #pragma unroll
            for (int i = 0; i < PM; i++) {
                float4 v;
                v.x = nw[0] + p[i] * vp.x + a[i].x;
                v.y = nw[1] + p[i] * vp.y + a[i].y;
                v.z = nw[2] + p[i] * vp.z + a[i].z;
                v.w = nw[3] + p[i] * vp.w + a[i].w;
                __stcs(reinterpret_cast<float4*>(
                           &out2[((b * PM + i) * MN + j) * PD + d0]), v);
            }
        }
    } else {
        // ---------- tail tile: checked ----------
        #pragma unroll
        for (int t = 0; t < JPW; t++) {
            const int j = jbase + 8 * t;
            if (j >= MN) break;

            const int nj = b * MN + j;
            const float f0 = __ldg(&g_feat[0][nj]);
            const float f1 = __ldg(&g_feat[1][nj]);
            const float f2 = __ldg(&g_feat[2][nj]);
            const float f3 = __ldg(&g_feat[3][nj]);
            const float f4 = __ldg(&g_feat[4][nj]);

            float nw[4];
            #pragma unroll
            for (int r = 0; r < 4; r++)
                nw[r] = f0 * wnc[r][0] + f1 * wnc[r][1] + f2 * wnc[r][2]
                      + f3 * wnc[r][3] + f4 * wnc[r][4];

            float p[PM];
            #pragma unroll
            for (int i = 0; i < PM; i++)
                p[i] = __ldg(&pref[(b * PM + i) * MN + j]);

            #pragma unroll
            for (int i = 0; i < PM; i++) {
                float4 v;
                v.x = nw[0] + p[i] * vp.x + a[i].x;
                v.y = nw[1] + p[i] * vp.y + a[i].y;
                v.z = nw[2] + p[i] * vp.z + a[i].z;
                v.w = nw[3] + p[i] * vp.w + a[i].w;
                __stcs(reinterpret_cast<float4*>(
                           &out2[((b * PM + i) * MN + j) * PD + d0]), v);
            }
        }
    }
}

// ---------------------------------------------------------------------------
extern "C" void kernel_launch(void* const* d_in, const int* in_sizes, int n_in,
                              void* d_out, int out_size)
{
    const float* locs      = (const float*)d_in[0];
    const float* capacity  = (const float*)d_in[1];
    const float* speed     = (const float*)d_in[2];
    const float* demand    = (const float*)d_in[3];
    const float* pref      = (const float*)d_in[4];
    // d_in[5] = action_mask (bool) — unused
    const float* W_depot   = (const float*)d_in[6];
    const float* W_posproj = (const float*)d_in[7];
    const float* alpha     = (const float*)d_in[8];
    const float* W_agents  = (const float*)d_in[9];
    const float* W_da      = (const float*)d_in[10];
    const float* W_clients = (const float*)d_in[11];
    const float* W_pref    = (const float*)d_in[12];
    const float* W_final   = (const float*)d_in[13];
    float* out = (float*)d_out;

    k_pre<<<PRE_BLKS, 256>>>(W_posproj, alpha, W_final, W_pref, W_clients,
                             W_agents, locs, capacity, speed, demand,
                             W_depot, W_da);

    k_main<<<MAIN_BLKS, 256>>>(pref, W_agents, W_clients, out);
}